// round 3
// baseline (speedup 1.0000x reference)
#include <cuda_runtime.h>

// CausalSelfAttention: B=4, T=2048, H=1024, NH=16, HD=64, fp32.
// Stage 1: fused QKV projection GEMMs (one launch, grid.z in {0,1,2}),
//          128x128x16 tiles, 8x8 micro-tile, double-buffered smem.
// Stage 2: flash-attention (causal + additive mask), Bq=128 x Bk=64 tiles,
//          8x4 micro-tile, online softmax, 3 syncs per k-tile, 96KB dyn smem.

#define BB 4
#define TT 2048
#define HH 1024
#define NHH 16
#define HDD 64

// Scratch: Q,K,V in head-major layout [(b*NH+h)*T + t][HD]  (32 MB each)
__device__ float g_Q[BB * NHH * TT * HDD];
__device__ float g_K[BB * NHH * TT * HDD];
__device__ float g_V[BB * NHH * TT * HDD];

// ---------------------------------------------------------------------------
// QKV GEMM:  C[m][n] = sum_k X[m][k] * W[n][k] + bias[n]
// Tile: BM=128, BN=128, BK=16. 256 threads, 8x8 micro-tile (2x2 of 4x4).
// Double-buffered smem, register prefetch, one __syncthreads per k-tile.
// ---------------------------------------------------------------------------
__global__ __launch_bounds__(256, 2) void qkv_gemm(
    const float* __restrict__ X,
    const float* __restrict__ Wq, const float* __restrict__ bq,
    const float* __restrict__ Wk, const float* __restrict__ bk,
    const float* __restrict__ Wv, const float* __restrict__ bv)
{
    const int which = blockIdx.z;
    const float* __restrict__ W    = (which == 0) ? Wq : (which == 1) ? Wk : Wv;
    const float* __restrict__ bias = (which == 0) ? bq : (which == 1) ? bk : bv;
    float* __restrict__ out        = (which == 0) ? g_Q : (which == 1) ? g_K : g_V;

    __shared__ __align__(16) float As[2][16][132];  // A^T [k][m], padded
    __shared__ __align__(16) float Bs[2][16][132];  // W^T [k][n], padded

    const int tid = threadIdx.x;
    const int tx  = tid & 15;   // n-dir
    const int ty  = tid >> 4;   // m-dir
    const int m0  = blockIdx.y * 128;
    const int n0  = blockIdx.x * 128;

    const int lrow = tid >> 1;        // 0..127
    const int lk   = (tid & 1) * 8;   // 0 or 8

    float acc[8][8];
#pragma unroll
    for (int i = 0; i < 8; i++)
#pragma unroll
        for (int j = 0; j < 8; j++) acc[i][j] = 0.0f;

    const float* Xp = X + (size_t)(m0 + lrow) * 1024 + lk;
    const float* Wp = W + (size_t)(n0 + lrow) * 1024 + lk;

    // prologue: tile 0 -> buffer 0
    {
        float4 a0 = *(const float4*)(Xp + 0);
        float4 a1 = *(const float4*)(Xp + 4);
        float4 b0 = *(const float4*)(Wp + 0);
        float4 b1 = *(const float4*)(Wp + 4);
        As[0][lk + 0][lrow] = a0.x;  As[0][lk + 1][lrow] = a0.y;
        As[0][lk + 2][lrow] = a0.z;  As[0][lk + 3][lrow] = a0.w;
        As[0][lk + 4][lrow] = a1.x;  As[0][lk + 5][lrow] = a1.y;
        As[0][lk + 6][lrow] = a1.z;  As[0][lk + 7][lrow] = a1.w;
        Bs[0][lk + 0][lrow] = b0.x;  Bs[0][lk + 1][lrow] = b0.y;
        Bs[0][lk + 2][lrow] = b0.z;  Bs[0][lk + 3][lrow] = b0.w;
        Bs[0][lk + 4][lrow] = b1.x;  Bs[0][lk + 5][lrow] = b1.y;
        Bs[0][lk + 6][lrow] = b1.z;  Bs[0][lk + 7][lrow] = b1.w;
    }
    __syncthreads();

    int buf = 0;
    for (int kt = 0; kt < 64; kt++) {
        float4 pa0, pa1, pb0, pb1;
        if (kt < 63) {
            const int ko = (kt + 1) * 16;
            pa0 = *(const float4*)(Xp + ko + 0);
            pa1 = *(const float4*)(Xp + ko + 4);
            pb0 = *(const float4*)(Wp + ko + 0);
            pb1 = *(const float4*)(Wp + ko + 4);
        }

#pragma unroll
        for (int k = 0; k < 16; k++) {
            float a[8], b[8];
            *(float4*)&a[0] = *(const float4*)&As[buf][k][ty * 4];
            *(float4*)&a[4] = *(const float4*)&As[buf][k][64 + ty * 4];
            *(float4*)&b[0] = *(const float4*)&Bs[buf][k][tx * 4];
            *(float4*)&b[4] = *(const float4*)&Bs[buf][k][64 + tx * 4];
#pragma unroll
            for (int i = 0; i < 8; i++)
#pragma unroll
                for (int j = 0; j < 8; j++)
                    acc[i][j] += a[i] * b[j];
        }

        if (kt < 63) {
            const int nb = buf ^ 1;
            As[nb][lk + 0][lrow] = pa0.x;  As[nb][lk + 1][lrow] = pa0.y;
            As[nb][lk + 2][lrow] = pa0.z;  As[nb][lk + 3][lrow] = pa0.w;
            As[nb][lk + 4][lrow] = pa1.x;  As[nb][lk + 5][lrow] = pa1.y;
            As[nb][lk + 6][lrow] = pa1.z;  As[nb][lk + 7][lrow] = pa1.w;
            Bs[nb][lk + 0][lrow] = pb0.x;  Bs[nb][lk + 1][lrow] = pb0.y;
            Bs[nb][lk + 2][lrow] = pb0.z;  Bs[nb][lk + 3][lrow] = pb0.w;
            Bs[nb][lk + 4][lrow] = pb1.x;  Bs[nb][lk + 5][lrow] = pb1.y;
            Bs[nb][lk + 6][lrow] = pb1.z;  Bs[nb][lk + 7][lrow] = pb1.w;
            __syncthreads();
            buf = nb;
        }
    }

    // epilogue: bias + head-major store
#pragma unroll
    for (int c = 0; c < 2; c++) {
        const int ncol = n0 + c * 64 + tx * 4;
        const int h    = ncol >> 6;
        const int d    = ncol & 63;
        float4 bv4 = *(const float4*)(bias + ncol);
#pragma unroll
        for (int r = 0; r < 2; r++) {
#pragma unroll
            for (int i = 0; i < 4; i++) {
                const int m = m0 + r * 64 + ty * 4 + i;
                const int b = m >> 11;
                const int t = m & 2047;
                const int ai = r * 4 + i;
                const int aj = c * 4;
                float4 o;
                o.x = acc[ai][aj + 0] + bv4.x;
                o.y = acc[ai][aj + 1] + bv4.y;
                o.z = acc[ai][aj + 2] + bv4.z;
                o.w = acc[ai][aj + 3] + bv4.w;
                *(float4*)&out[(((size_t)(b * NHH + h)) * TT + t) * HDD + d] = o;
            }
        }
    }
}

// ---------------------------------------------------------------------------
// Flash attention, fp32, causal, additive mask. Bq=128, Bk=64.
// Block: one (b, h, q-tile of 128 rows). 256 threads (16x16).
// Per thread: S rows 8*ty+i (i<8), S cols tx+16*j (j<4); O cols 4*tx+j.
// Dynamic smem (96KB): Qs[128*64], Ks[64*64], Vs[64*64], Ps[128*64],
// all XOR-swizzled. 3 __syncthreads per k-tile.
// ---------------------------------------------------------------------------
#define SWI(r, d) (((r) << 6) + (((((d) >> 2) ^ ((r) & 7)) << 2) | ((d) & 3)))

#define QS_OFF 0
#define KS_OFF (128 * 64)
#define VS_OFF (128 * 64 + 64 * 64)
#define PS_OFF (128 * 64 + 64 * 64 + 64 * 64)
#define SMEM_FLOATS (128 * 64 + 64 * 64 + 64 * 64 + 128 * 64)

__global__ __launch_bounds__(256) void attn_kernel(
    const float* __restrict__ mask,   // [B, T] additive (from [B,1,1,T])
    float* __restrict__ out)          // [B, T, H]
{
    extern __shared__ __align__(16) float sm[];
    float* Qs = sm + QS_OFF;
    float* Ks = sm + KS_OFF;
    float* Vs = sm + VS_OFF;
    float* Ps = sm + PS_OFF;

    const int tid = threadIdx.x;
    const int tx  = tid & 15;
    const int ty  = tid >> 4;
    const int qt  = blockIdx.x;   // 0..15
    const int h   = blockIdx.y;   // 0..15
    const int b   = blockIdx.z;   // 0..3

    const size_t bh_base = ((size_t)(b * NHH + h)) * TT * HDD;
    const float* __restrict__ Qg = g_Q + bh_base + (size_t)qt * 128 * HDD;
    const float* __restrict__ Kg = g_K + bh_base;
    const float* __restrict__ Vg = g_V + bh_base;
    const float* __restrict__ mrow = mask + (size_t)b * TT;

    const int lr = tid >> 2;          // 0..63
    const int ld = (tid & 3) * 16;    // 0,16,32,48

    // Load Q tile (128 rows), once
#pragma unroll
    for (int rr = 0; rr < 128; rr += 64) {
#pragma unroll
        for (int j = 0; j < 4; j++) {
            float4 v = *(const float4*)(Qg + (size_t)(lr + rr) * HDD + ld + 4 * j);
            *(float4*)&Qs[SWI(lr + rr, ld + 4 * j)] = v;
        }
    }

    float m_run[8], l_run[8], o_acc[8][4];
#pragma unroll
    for (int i = 0; i < 8; i++) {
        m_run[i] = -1e30f;
        l_run[i] = 0.0f;
#pragma unroll
        for (int j = 0; j < 4; j++) o_acc[i][j] = 0.0f;
    }

    const float scale = 0.125f;   // HD^-0.5 = 1/8
    const int q0 = qt * 128;
    const int r_base = 8 * ty;
    const int nkt = 2 * qt + 2;   // k-tiles covering rows [0, q0+128)

    for (int kt = 0; kt < nkt; kt++) {
        const int k0 = kt * 64;

        // sync A: prior-iteration S reads of Ks and PV reads of Vs/Ps are done
        // (also covers the initial Qs stores on iteration 0)
        __syncthreads();
#pragma unroll
        for (int j = 0; j < 4; j++) {
            float4 kv = *(const float4*)(Kg + (size_t)(k0 + lr) * HDD + ld + 4 * j);
            *(float4*)&Ks[SWI(lr, ld + 4 * j)] = kv;
            float4 vv = *(const float4*)(Vg + (size_t)(k0 + lr) * HDD + ld + 4 * j);
            *(float4*)&Vs[SWI(lr, ld + 4 * j)] = vv;
        }
        __syncthreads();  // sync B: K/V visible

        // ---- S = Q @ K^T (per-thread 8x4) ----
        float s[8][4];
#pragma unroll
        for (int i = 0; i < 8; i++)
#pragma unroll
            for (int j = 0; j < 4; j++) s[i][j] = 0.0f;

#pragma unroll
        for (int d = 0; d < 64; d += 4) {
            float4 qv[8], kv[4];
#pragma unroll
            for (int i = 0; i < 8; i++)
                qv[i] = *(const float4*)&Qs[SWI(r_base + i, d)];
#pragma unroll
            for (int j = 0; j < 4; j++)
                kv[j] = *(const float4*)&Ks[SWI(tx + 16 * j, d)];
#pragma unroll
            for (int i = 0; i < 8; i++)
#pragma unroll
                for (int j = 0; j < 4; j++)
                    s[i][j] += qv[i].x * kv[j].x + qv[i].y * kv[j].y +
                               qv[i].z * kv[j].z + qv[i].w * kv[j].w;
        }

        // additive mask for this thread's 4 columns
        float am[4];
#pragma unroll
        for (int j = 0; j < 4; j++) am[j] = __ldg(&mrow[k0 + tx + 16 * j]);

        // scale + causal + additive mask
#pragma unroll
        for (int i = 0; i < 8; i++) {
            const int q = q0 + r_base + i;
#pragma unroll
            for (int j = 0; j < 4; j++) {
                const int k = k0 + tx + 16 * j;
                float v = s[i][j] * scale + am[j];
                s[i][j] = (k > q) ? -1e30f : v;
            }
        }

        // ---- online softmax (rows reduced across 16 lanes) ----
#pragma unroll
        for (int i = 0; i < 8; i++) {
            float mx = fmaxf(fmaxf(s[i][0], s[i][1]), fmaxf(s[i][2], s[i][3]));
#pragma unroll
            for (int off = 8; off >= 1; off >>= 1)
                mx = fmaxf(mx, __shfl_xor_sync(0xffffffffu, mx, off));
            const float mnew  = fmaxf(m_run[i], mx);
            const float alpha = __expf(m_run[i] - mnew);
            m_run[i] = mnew;

            float ls = 0.0f;
#pragma unroll
            for (int j = 0; j < 4; j++) {
                s[i][j] = __expf(s[i][j] - mnew);
                ls += s[i][j];
            }
#pragma unroll
            for (int off = 8; off >= 1; off >>= 1)
                ls += __shfl_xor_sync(0xffffffffu, ls, off);
            l_run[i] = l_run[i] * alpha + ls;
#pragma unroll
            for (int j = 0; j < 4; j++) o_acc[i][j] *= alpha;
        }

        // write P (prior-iter readers of Ps finished before sync A)
#pragma unroll
        for (int i = 0; i < 8; i++)
#pragma unroll
            for (int j = 0; j < 4; j++)
                Ps[SWI(r_base + i, tx + 16 * j)] = s[i][j];
        __syncthreads();  // sync C: P visible

        // ---- O += P @ V ----
#pragma unroll
        for (int c = 0; c < 64; c += 4) {
            float4 pv[8], vv[4];
#pragma unroll
            for (int i = 0; i < 8; i++)
                pv[i] = *(const float4*)&Ps[SWI(r_base + i, c)];
#pragma unroll
            for (int cc = 0; cc < 4; cc++)
                vv[cc] = *(const float4*)&Vs[SWI(c + cc, 4 * tx)];
#pragma unroll
            for (int i = 0; i < 8; i++) {
                o_acc[i][0] += pv[i].x * vv[0].x + pv[i].y * vv[1].x +
                               pv[i].z * vv[2].x + pv[i].w * vv[3].x;
                o_acc[i][1] += pv[i].x * vv[0].y + pv[i].y * vv[1].y +
                               pv[i].z * vv[2].y + pv[i].w * vv[3].y;
                o_acc[i][2] += pv[i].x * vv[0].z + pv[i].y * vv[1].z +
                               pv[i].z * vv[2].z + pv[i].w * vv[3].z;
                o_acc[i][3] += pv[i].x * vv[0].w + pv[i].y * vv[1].w +
                               pv[i].z * vv[2].w + pv[i].w * vv[3].w;
            }
        }
    }

    // ---- normalize + write out [B, T, H] ----
#pragma unroll
    for (int i = 0; i < 8; i++) {
        const float inv = 1.0f / l_run[i];
        const int q = q0 + r_base + i;
        float4 o;
        o.x = o_acc[i][0] * inv;
        o.y = o_acc[i][1] * inv;
        o.z = o_acc[i][2] * inv;
        o.w = o_acc[i][3] * inv;
        *(float4*)&out[((size_t)b * TT + q) * HH + h * HDD + 4 * tx] = o;
    }
}

// ---------------------------------------------------------------------------
extern "C" void kernel_launch(void* const* d_in, const int* in_sizes, int n_in,
                              void* d_out, int out_size)
{
    (void)in_sizes; (void)n_in; (void)out_size;
    const float* X    = (const float*)d_in[0];   // hidden_states [4,2048,1024]
    const float* mask = (const float*)d_in[1];   // attention_mask [4,1,1,2048]
    const float* Wq   = (const float*)d_in[2];
    const float* bq   = (const float*)d_in[3];
    const float* Wk   = (const float*)d_in[4];
    const float* bk   = (const float*)d_in[5];
    const float* Wv   = (const float*)d_in[6];
    const float* bv   = (const float*)d_in[7];
    float* out = (float*)d_out;

    // QKV projections: grid (N-tiles=8, M-tiles=64, {q,k,v}=3)
    qkv_gemm<<<dim3(8, 64, 3), 256>>>(X, Wq, bq, Wk, bk, Wv, bv);

    // Attention: 96KB dynamic smem
    const int smem_bytes = SMEM_FLOATS * (int)sizeof(float);
    cudaFuncSetAttribute(attn_kernel,
                         cudaFuncAttributeMaxDynamicSharedMemorySize, smem_bytes);
    attn_kernel<<<dim3(16, 16, 4), 256, smem_bytes>>>(mask, out);
}

// round 10
// speedup vs baseline: 1.0544x; 1.0544x over previous
#include <cuda_runtime.h>
#include <cuda_bf16.h>
#include <cstdint>

// CausalSelfAttention: B=4, T=2048, H=1024, NH=16, HD=64, fp32.
// Stage 0: fp32 -> (bf16 hi, bf16 lo) split of X and Wq/Wk/Wv.
// Stage 1: QKV projection via mma.sync bf16 HMMA (PTX baseline feature set),
//          3-term split (hh + hl + lh), fp32 register accumulation.
// Stage 2: fp32 flash-attention, 2 CTAs/SM.

#define BB 4
#define TT 2048
#define HH 1024
#define NHH 16
#define HDD 64

// fp32 Q,K,V in head-major layout [(b*NH+h)*T + t][HD]
__device__ float g_Q[BB * NHH * TT * HDD];
__device__ float g_K[BB * NHH * TT * HDD];
__device__ float g_V[BB * NHH * TT * HDD];

// bf16 hi/lo split scratch
__device__ __nv_bfloat16 g_Xh[8192 * 1024];
__device__ __nv_bfloat16 g_Xl[8192 * 1024];
__device__ __nv_bfloat16 g_Wh[3 * 1024 * 1024];
__device__ __nv_bfloat16 g_Wl[3 * 1024 * 1024];

// ---------------------------------------------------------------------------
__device__ __forceinline__ uint32_t smem_u32(const void* p) {
    uint32_t a;
    asm("{ .reg .u64 t; cvta.to.shared.u64 t, %1; cvt.u32.u64 %0, t; }"
        : "=r"(a) : "l"(p));
    return a;
}

#define SWZ128(bo) ((bo) ^ (((bo) >> 3) & 0x70))

__device__ __forceinline__ void ldsm_x4(uint32_t* d, uint32_t addr) {
    asm volatile("ldmatrix.sync.aligned.m8n8.x4.shared.b16 {%0,%1,%2,%3}, [%4];"
                 : "=r"(d[0]), "=r"(d[1]), "=r"(d[2]), "=r"(d[3]) : "r"(addr));
}
__device__ __forceinline__ void mma16816(float* c, const uint32_t* a,
                                         uint32_t b0, uint32_t b1) {
    asm volatile(
        "mma.sync.aligned.m16n8k16.row.col.f32.bf16.bf16.f32 "
        "{%0,%1,%2,%3}, {%4,%5,%6,%7}, {%8,%9}, {%0,%1,%2,%3};"
        : "+f"(c[0]), "+f"(c[1]), "+f"(c[2]), "+f"(c[3])
        : "r"(a[0]), "r"(a[1]), "r"(a[2]), "r"(a[3]), "r"(b0), "r"(b1));
}

// ---------------------------------------------------------------------------
// Stage 0: fp32 -> bf16 hi/lo split (vectorized by 4)
// dst_sel: 0 = X, 1/2/3 = Wq/Wk/Wv
// ---------------------------------------------------------------------------
__global__ __launch_bounds__(256) void convert_split(
    const float* __restrict__ src, int n4, int dst_sel)
{
    __nv_bfloat16* hi;
    __nv_bfloat16* lo;
    if (dst_sel == 0)      { hi = g_Xh; lo = g_Xl; }
    else                   { hi = g_Wh + (size_t)(dst_sel - 1) * 1048576;
                             lo = g_Wl + (size_t)(dst_sel - 1) * 1048576; }

    int i = blockIdx.x * 256 + threadIdx.x;
    if (i >= n4) return;
    float4 v = ((const float4*)src)[i];

    __nv_bfloat16 h0 = __float2bfloat16_rn(v.x);
    __nv_bfloat16 h1 = __float2bfloat16_rn(v.y);
    __nv_bfloat16 h2 = __float2bfloat16_rn(v.z);
    __nv_bfloat16 h3 = __float2bfloat16_rn(v.w);
    __nv_bfloat16 l0 = __float2bfloat16_rn(v.x - __bfloat162float(h0));
    __nv_bfloat16 l1 = __float2bfloat16_rn(v.y - __bfloat162float(h1));
    __nv_bfloat16 l2 = __float2bfloat16_rn(v.z - __bfloat162float(h2));
    __nv_bfloat16 l3 = __float2bfloat16_rn(v.w - __bfloat162float(h3));

    __nv_bfloat162* hp = (__nv_bfloat162*)hi;
    __nv_bfloat162* lp = (__nv_bfloat162*)lo;
    hp[2 * i + 0] = __nv_bfloat162(h0, h1);
    hp[2 * i + 1] = __nv_bfloat162(h2, h3);
    lp[2 * i + 0] = __nv_bfloat162(l0, l1);
    lp[2 * i + 1] = __nv_bfloat162(l2, l3);
}

// ---------------------------------------------------------------------------
// Stage 1: bf16 HMMA QKV GEMM.
// C[m][n] = sum_k X[m][k] * W[n][k] + bias[n]  via  Xh@Wh + Xh@Wl + Xl@Wh.
// Per CTA: M=128, N=128, K=1024 in 16 chunks of 64. 256 threads = 8 warps,
// each warp a 64x32 C tile (4 x m16 * 4 x n8 mma fragments).
// SMEM (dynamic 64KB): AH/AL/BH/BL, each 128 rows x 128B, SW128 swizzle.
// ---------------------------------------------------------------------------
#define G_AH 0
#define G_AL 16384
#define G_BH 32768
#define G_BL 49152
#define G_SMEM_BYTES 65536

__global__ __launch_bounds__(256) void qkv_gemm_mma(
    const float* __restrict__ bq,
    const float* __restrict__ bk,
    const float* __restrict__ bv)
{
    extern __shared__ __align__(16) char sm[];
    const uint32_t smem_base = smem_u32(sm);

    const int tid  = threadIdx.x;
    const int wid  = tid >> 5;
    const int lane = tid & 31;
    const int which = blockIdx.z;
    const int n0 = blockIdx.x * 128;
    const int m0 = blockIdx.y * 128;

    const float* __restrict__ bias = (which == 0) ? bq : (which == 1) ? bk : bv;
    float* __restrict__ out        = (which == 0) ? g_Q : (which == 1) ? g_K : g_V;

    // warp tile: wm in {0,1} (64 rows), wn in {0..3} (32 cols)
    const int wm = wid & 1;
    const int wn = wid >> 1;

    float acc[4][4][4];
#pragma unroll
    for (int i = 0; i < 4; i++)
#pragma unroll
        for (int j = 0; j < 4; j++)
#pragma unroll
            for (int c = 0; c < 4; c++) acc[i][j][c] = 0.0f;

    // global tile-load indexing: 2 threads per row, 64B halves
    const int lrow  = tid >> 1;          // 0..127
    const int lhalf = (tid & 1) * 32;    // bf16 element offset: 0 or 32

    const __nv_bfloat16* Ah = g_Xh + (size_t)(m0 + lrow) * 1024 + lhalf;
    const __nv_bfloat16* Al = g_Xl + (size_t)(m0 + lrow) * 1024 + lhalf;
    const __nv_bfloat16* Bh = g_Wh + (size_t)which * 1048576 +
                              (size_t)(n0 + lrow) * 1024 + lhalf;
    const __nv_bfloat16* Bl = g_Wl + (size_t)which * 1048576 +
                              (size_t)(n0 + lrow) * 1024 + lhalf;

    // ldmatrix per-lane addressing
    const int arow  = lane & 15;              // A: rows 0-15 twice
    const int acolb = (lane >> 4) << 4;       // A: byte 0 / 16
    const int brow  = (lane & 7) | (((lane >> 4) & 1) << 3);  // B: n row
    const int bcolb = ((lane >> 3) & 1) << 4; // B: byte 0 / 16

    for (int kc = 0; kc < 16; kc++) {
        __syncthreads();   // previous chunk's ldmatrix reads done

        const int ko = kc * 64;
        uint4 rah[4], ral[4], rbh[4], rbl[4];
#pragma unroll
        for (int j = 0; j < 4; j++) {
            rah[j] = *(const uint4*)(Ah + ko + j * 8);
            ral[j] = *(const uint4*)(Al + ko + j * 8);
            rbh[j] = *(const uint4*)(Bh + ko + j * 8);
            rbl[j] = *(const uint4*)(Bl + ko + j * 8);
        }
#pragma unroll
        for (int j = 0; j < 4; j++) {
            const uint32_t bo = lrow * 128 + lhalf * 2 + j * 16;
            const uint32_t so = SWZ128(bo);
            *(uint4*)(sm + G_AH + so) = rah[j];
            *(uint4*)(sm + G_AL + so) = ral[j];
            *(uint4*)(sm + G_BH + so) = rbh[j];
            *(uint4*)(sm + G_BL + so) = rbl[j];
        }
        __syncthreads();   // tiles visible

        // 3 split terms (hh, hl, lh) x 4 k16-steps
#pragma unroll
        for (int sp = 0; sp < 3; sp++) {
            const uint32_t aoff = (sp == 2) ? G_AL : G_AH;
            const uint32_t boff = (sp == 1) ? G_BL : G_BH;
#pragma unroll
            for (int ks = 0; ks < 4; ks++) {
                const int kb = ks * 32;   // byte offset of this k16 in the row

                uint32_t afr[4][4];
#pragma unroll
                for (int mt = 0; mt < 4; mt++) {
                    const uint32_t bo =
                        (uint32_t)(wm * 64 + mt * 16 + arow) * 128 + kb + acolb;
                    ldsm_x4(afr[mt], smem_base + aoff + SWZ128(bo));
                }
                uint32_t bfr[2][4];
#pragma unroll
                for (int g = 0; g < 2; g++) {
                    const uint32_t bo =
                        (uint32_t)(wn * 32 + g * 16 + brow) * 128 + kb + bcolb;
                    ldsm_x4(bfr[g], smem_base + boff + SWZ128(bo));
                }
#pragma unroll
                for (int mt = 0; mt < 4; mt++)
#pragma unroll
                    for (int nt = 0; nt < 4; nt++)
                        mma16816(acc[mt][nt], afr[mt],
                                 bfr[nt >> 1][(nt & 1) * 2],
                                 bfr[nt >> 1][(nt & 1) * 2 + 1]);
            }
        }
    }

    // Epilogue: bias + head-major store straight from fragments.
    // acc[mt][nt]: c0,c1 -> (row r, cols cpair,cpair+1); c2,c3 -> row r+8.
    const int r     = lane >> 2;
    const int cpair = (lane & 3) * 2;
#pragma unroll
    for (int nt = 0; nt < 4; nt++) {
        const int n_g = n0 + wn * 32 + nt * 8 + cpair;
        const int h   = n_g >> 6;
        const int d   = n_g & 63;
        const float2 b2 = *(const float2*)(bias + n_g);
#pragma unroll
        for (int mt = 0; mt < 4; mt++) {
#pragma unroll
            for (int half = 0; half < 2; half++) {
                const int m_g = m0 + wm * 64 + mt * 16 + r + half * 8;
                const int bb  = m_g >> 11;
                const int t   = m_g & 2047;
                float2 o;
                o.x = acc[mt][nt][half * 2 + 0] + b2.x;
                o.y = acc[mt][nt][half * 2 + 1] + b2.y;
                *(float2*)&out[(((size_t)(bb * NHH + h)) * TT + t) * HDD + d] = o;
            }
        }
    }
}

// ---------------------------------------------------------------------------
// Stage 2: flash attention, fp32, causal, additive mask. Bq=128, Bk=64.
// 256 threads (16x16), 8x4 micro-tile, 96KB dyn smem, 2 CTAs/SM.
// ---------------------------------------------------------------------------
#define SWI(r, d) (((r) << 6) + (((((d) >> 2) ^ ((r) & 7)) << 2) | ((d) & 3)))

#define QS_OFF 0
#define KS_OFF (128 * 64)
#define VS_OFF (128 * 64 + 64 * 64)
#define PS_OFF (128 * 64 + 64 * 64 + 64 * 64)
#define SMEM_FLOATS (128 * 64 + 64 * 64 + 64 * 64 + 128 * 64)

__global__ __launch_bounds__(256, 2) void attn_kernel(
    const float* __restrict__ mask,   // [B, T] additive (from [B,1,1,T])
    float* __restrict__ out)          // [B, T, H]
{
    extern __shared__ __align__(16) float smA[];
    float* Qs = smA + QS_OFF;
    float* Ks = smA + KS_OFF;
    float* Vs = smA + VS_OFF;
    float* Ps = smA + PS_OFF;

    const int tid = threadIdx.x;
    const int tx  = tid & 15;
    const int ty  = tid >> 4;
    const int qt  = blockIdx.x;   // 0..15
    const int h   = blockIdx.y;   // 0..15
    const int b   = blockIdx.z;   // 0..3

    const size_t bh_base = ((size_t)(b * NHH + h)) * TT * HDD;
    const float* __restrict__ Qg = g_Q + bh_base + (size_t)qt * 128 * HDD;
    const float* __restrict__ Kg = g_K + bh_base;
    const float* __restrict__ Vg = g_V + bh_base;
    const float* __restrict__ mrow = mask + (size_t)b * TT;

    const int lr = tid >> 2;          // 0..63
    const int ld = (tid & 3) * 16;    // 0,16,32,48

#pragma unroll
    for (int rr = 0; rr < 128; rr += 64) {
#pragma unroll
        for (int j = 0; j < 4; j++) {
            float4 v = *(const float4*)(Qg + (size_t)(lr + rr) * HDD + ld + 4 * j);
            *(float4*)&Qs[SWI(lr + rr, ld + 4 * j)] = v;
        }
    }

    float m_run[8], l_run[8], o_acc[8][4];
#pragma unroll
    for (int i = 0; i < 8; i++) {
        m_run[i] = -1e30f;
        l_run[i] = 0.0f;
#pragma unroll
        for (int j = 0; j < 4; j++) o_acc[i][j] = 0.0f;
    }

    const float scale = 0.125f;
    const int q0 = qt * 128;
    const int r_base = 8 * ty;
    const int nkt = 2 * qt + 2;

    for (int kt = 0; kt < nkt; kt++) {
        const int k0 = kt * 64;

        __syncthreads();
#pragma unroll
        for (int j = 0; j < 4; j++) {
            float4 kv = *(const float4*)(Kg + (size_t)(k0 + lr) * HDD + ld + 4 * j);
            *(float4*)&Ks[SWI(lr, ld + 4 * j)] = kv;
            float4 vv = *(const float4*)(Vg + (size_t)(k0 + lr) * HDD + ld + 4 * j);
            *(float4*)&Vs[SWI(lr, ld + 4 * j)] = vv;
        }
        __syncthreads();

        float s[8][4];
#pragma unroll
        for (int i = 0; i < 8; i++)
#pragma unroll
            for (int j = 0; j < 4; j++) s[i][j] = 0.0f;

#pragma unroll
        for (int d = 0; d < 64; d += 4) {
            float4 qv[8], kv[4];
#pragma unroll
            for (int i = 0; i < 8; i++)
                qv[i] = *(const float4*)&Qs[SWI(r_base + i, d)];
#pragma unroll
            for (int j = 0; j < 4; j++)
                kv[j] = *(const float4*)&Ks[SWI(tx + 16 * j, d)];
#pragma unroll
            for (int i = 0; i < 8; i++)
#pragma unroll
                for (int j = 0; j < 4; j++)
                    s[i][j] += qv[i].x * kv[j].x + qv[i].y * kv[j].y +
                               qv[i].z * kv[j].z + qv[i].w * kv[j].w;
        }

        float am[4];
#pragma unroll
        for (int j = 0; j < 4; j++) am[j] = __ldg(&mrow[k0 + tx + 16 * j]);

#pragma unroll
        for (int i = 0; i < 8; i++) {
            const int q = q0 + r_base + i;
#pragma unroll
            for (int j = 0; j < 4; j++) {
                const int k = k0 + tx + 16 * j;
                float v = s[i][j] * scale + am[j];
                s[i][j] = (k > q) ? -1e30f : v;
            }
        }

#pragma unroll
        for (int i = 0; i < 8; i++) {
            float mx = fmaxf(fmaxf(s[i][0], s[i][1]), fmaxf(s[i][2], s[i][3]));
#pragma unroll
            for (int off = 8; off >= 1; off >>= 1)
                mx = fmaxf(mx, __shfl_xor_sync(0xffffffffu, mx, off));
            const float mnew  = fmaxf(m_run[i], mx);
            const float alpha = __expf(m_run[i] - mnew);
            m_run[i] = mnew;

            float ls = 0.0f;
#pragma unroll
            for (int j = 0; j < 4; j++) {
                s[i][j] = __expf(s[i][j] - mnew);
                ls += s[i][j];
            }
#pragma unroll
            for (int off = 8; off >= 1; off >>= 1)
                ls += __shfl_xor_sync(0xffffffffu, ls, off);
            l_run[i] = l_run[i] * alpha + ls;
#pragma unroll
            for (int j = 0; j < 4; j++) o_acc[i][j] *= alpha;
        }

#pragma unroll
        for (int i = 0; i < 8; i++)
#pragma unroll
            for (int j = 0; j < 4; j++)
                Ps[SWI(r_base + i, tx + 16 * j)] = s[i][j];
        __syncthreads();

#pragma unroll
        for (int c = 0; c < 64; c += 4) {
            float4 pv[8], vv[4];
#pragma unroll
            for (int i = 0; i < 8; i++)
                pv[i] = *(const float4*)&Ps[SWI(r_base + i, c)];
#pragma unroll
            for (int cc = 0; cc < 4; cc++)
                vv[cc] = *(const float4*)&Vs[SWI(c + cc, 4 * tx)];
#pragma unroll
            for (int i = 0; i < 8; i++) {
                o_acc[i][0] += pv[i].x * vv[0].x + pv[i].y * vv[1].x +
                               pv[i].z * vv[2].x + pv[i].w * vv[3].x;
                o_acc[i][1] += pv[i].x * vv[0].y + pv[i].y * vv[1].y +
                               pv[i].z * vv[2].y + pv[i].w * vv[3].y;
                o_acc[i][2] += pv[i].x * vv[0].z + pv[i].y * vv[1].z +
                               pv[i].z * vv[2].z + pv[i].w * vv[3].z;
                o_acc[i][3] += pv[i].x * vv[0].w + pv[i].y * vv[1].w +
                               pv[i].z * vv[2].w + pv[i].w * vv[3].w;
            }
        }
    }

#pragma unroll
    for (int i = 0; i < 8; i++) {
        const float inv = 1.0f / l_run[i];
        const int q = q0 + r_base + i;
        float4 o;
        o.x = o_acc[i][0] * inv;
        o.y = o_acc[i][1] * inv;
        o.z = o_acc[i][2] * inv;
        o.w = o_acc[i][3] * inv;
        *(float4*)&out[((size_t)b * TT + q) * HH + h * HDD + 4 * tx] = o;
    }
}

// ---------------------------------------------------------------------------
extern "C" void kernel_launch(void* const* d_in, const int* in_sizes, int n_in,
                              void* d_out, int out_size)
{
    (void)in_sizes; (void)n_in; (void)out_size;
    const float* X    = (const float*)d_in[0];   // hidden_states [4,2048,1024]
    const float* mask = (const float*)d_in[1];   // attention_mask [4,1,1,2048]
    const float* Wq   = (const float*)d_in[2];
    const float* bq   = (const float*)d_in[3];
    const float* Wk   = (const float*)d_in[4];
    const float* bk   = (const float*)d_in[5];
    const float* Wv   = (const float*)d_in[6];
    const float* bv   = (const float*)d_in[7];
    float* out = (float*)d_out;

    // Stage 0: split conversion
    const int nX4 = 8192 * 1024 / 4;
    const int nW4 = 1024 * 1024 / 4;
    convert_split<<<(nX4 + 255) / 256, 256>>>(X,  nX4, 0);
    convert_split<<<(nW4 + 255) / 256, 256>>>(Wq, nW4, 1);
    convert_split<<<(nW4 + 255) / 256, 256>>>(Wk, nW4, 2);
    convert_split<<<(nW4 + 255) / 256, 256>>>(Wv, nW4, 3);

    // Stage 1: HMMA QKV GEMM (N-tiles=8, M-tiles=64, {q,k,v}=3)
    cudaFuncSetAttribute(qkv_gemm_mma,
                         cudaFuncAttributeMaxDynamicSharedMemorySize, G_SMEM_BYTES);
    qkv_gemm_mma<<<dim3(8, 64, 3), 256, G_SMEM_BYTES>>>(bq, bk, bv);

    // Stage 2: attention (96KB dyn smem, 2 CTAs/SM)
    const int smem_bytes = SMEM_FLOATS * (int)sizeof(float);
    cudaFuncSetAttribute(attn_kernel,
                         cudaFuncAttributeMaxDynamicSharedMemorySize, smem_bytes);
    attn_kernel<<<dim3(16, 16, 4), 256, smem_bytes>>>(mask, out);
}